// round 3
// baseline (speedup 1.0000x reference)
#include <cuda_runtime.h>
#include <cuda_fp16.h>

#define NROWS 8192
#define DDIM  512
#define NTRIP 200000

// Scratch (allocation-free rule: __device__ globals)
__device__ __align__(16) __half g_xh [NROWS * DDIM];  // fp16 x rows (8 MB)
__device__ __align__(16) __half g_ynh[NROWS * DDIM];  // fp16 normalized y rows (8 MB)
__device__ float  g_sqx[NROWS];                       // exact fp32 ||x||^2
__device__ double g_accum;

__device__ __forceinline__ __half2 as_h2(unsigned u) { return *(__half2*)&u; }

// ---------------------------------------------------------------------------
// prep: warp-per-row. ||x||^2 (fp32 exact), x -> fp16, y normalized -> fp16.
// 1024 blocks x 256 threads (8 warps); lane owns 4 float4 per array.
// ---------------------------------------------------------------------------
__global__ __launch_bounds__(256)
void prep_kernel(const float* __restrict__ x,
                 const float* __restrict__ y,
                 const float* __restrict__ norm_s) {
    const int warp = threadIdx.x >> 5;
    const int lane = threadIdx.x & 31;
    const int row  = blockIdx.x * 8 + warp;
    if (row == 0 && lane == 0) g_accum = 0.0;

    const float4* xr = (const float4*)(x + (size_t)row * DDIM);
    const float4* yr = (const float4*)(y + (size_t)row * DDIM);

    float4 xv[4], yv[4];
    #pragma unroll
    for (int it = 0; it < 4; ++it) {
        xv[it] = xr[it * 32 + lane];
        yv[it] = yr[it * 32 + lane];
    }

    float sx = 0.f, sy = 0.f;
    #pragma unroll
    for (int it = 0; it < 4; ++it) {
        sx = fmaf(xv[it].x, xv[it].x, sx); sx = fmaf(xv[it].y, xv[it].y, sx);
        sx = fmaf(xv[it].z, xv[it].z, sx); sx = fmaf(xv[it].w, xv[it].w, sx);
        sy = fmaf(yv[it].x, yv[it].x, sy); sy = fmaf(yv[it].y, yv[it].y, sy);
        sy = fmaf(yv[it].z, yv[it].z, sy); sy = fmaf(yv[it].w, yv[it].w, sy);
    }
    #pragma unroll
    for (int off = 16; off; off >>= 1) {
        sx += __shfl_xor_sync(0xFFFFFFFFu, sx, off);
        sy += __shfl_xor_sync(0xFFFFFFFFu, sy, off);
    }
    if (lane == 0) g_sqx[row] = sx;

    const float scale = norm_s[0] * rsqrtf(sy);

    uint2* xo = (uint2*)(g_xh  + (size_t)row * DDIM);
    uint2* yo = (uint2*)(g_ynh + (size_t)row * DDIM);
    #pragma unroll
    for (int it = 0; it < 4; ++it) {
        __half2 hx0 = __floats2half2_rn(xv[it].x, xv[it].y);
        __half2 hx1 = __floats2half2_rn(xv[it].z, xv[it].w);
        uint2 wx; wx.x = *(unsigned*)&hx0; wx.y = *(unsigned*)&hx1;
        xo[it * 32 + lane] = wx;

        __half2 hy0 = __floats2half2_rn(yv[it].x * scale, yv[it].y * scale);
        __half2 hy1 = __floats2half2_rn(yv[it].z * scale, yv[it].w * scale);
        uint2 wy; wy.x = *(unsigned*)&hy0; wy.y = *(unsigned*)&hy1;
        yo[it * 32 + lane] = wy;
    }
}

// ---------------------------------------------------------------------------
// triplet kernel: one warp per triplet, fp16 gathers, HFMA2 accumulation
// (one half2 accumulator per dot per lane; fp32 only for the warp reduce).
// ---------------------------------------------------------------------------
__device__ __forceinline__ float softplus_f(float z) {
    return fmaxf(z, 0.0f) + log1pf(expf(-fabsf(z)));
}

__global__ __launch_bounds__(256, 8)
void triplet_kernel(const int* __restrict__ trips,
                    const float* __restrict__ norm_s) {
    const int warp = threadIdx.x >> 5;
    const int lane = threadIdx.x & 31;
    const int t = blockIdx.x * 8 + warp;

    float val = 0.0f;
    if (t < NTRIP) {
        const int i = trips[3 * t + 0];
        const int j = trips[3 * t + 1];
        const int k = trips[3 * t + 2];

        const uint4* xi = (const uint4*)(g_xh  + (size_t)i * DDIM);
        const uint4* xj = (const uint4*)(g_xh  + (size_t)j * DDIM);
        const uint4* xk = (const uint4*)(g_xh  + (size_t)k * DDIM);
        const uint4* yi = (const uint4*)(g_ynh + (size_t)i * DDIM);
        const uint4* yj = (const uint4*)(g_ynh + (size_t)j * DDIM);
        const uint4* yk = (const uint4*)(g_ynh + (size_t)k * DDIM);

        const __half2 z2 = __float2half2_rn(0.f);
        __half2 haxj = z2, haxk = z2, hayj = z2, hayk = z2;

        #pragma unroll
        for (int it = 0; it < 2; ++it) {
            const int c = it * 32 + lane;           // 64 uint4 per row
            const uint4 va = __ldg(&xi[c]);
            const uint4 vb = __ldg(&xj[c]);
            const uint4 vd = __ldg(&xk[c]);
            const uint4 vp = __ldg(&yi[c]);
            const uint4 vq = __ldg(&yj[c]);
            const uint4 vr = __ldg(&yk[c]);

            haxj = __hfma2(as_h2(va.x), as_h2(vb.x), haxj);
            haxj = __hfma2(as_h2(va.y), as_h2(vb.y), haxj);
            haxj = __hfma2(as_h2(va.z), as_h2(vb.z), haxj);
            haxj = __hfma2(as_h2(va.w), as_h2(vb.w), haxj);

            haxk = __hfma2(as_h2(va.x), as_h2(vd.x), haxk);
            haxk = __hfma2(as_h2(va.y), as_h2(vd.y), haxk);
            haxk = __hfma2(as_h2(va.z), as_h2(vd.z), haxk);
            haxk = __hfma2(as_h2(va.w), as_h2(vd.w), haxk);

            hayj = __hfma2(as_h2(vp.x), as_h2(vq.x), hayj);
            hayj = __hfma2(as_h2(vp.y), as_h2(vq.y), hayj);
            hayj = __hfma2(as_h2(vp.z), as_h2(vq.z), hayj);
            hayj = __hfma2(as_h2(vp.w), as_h2(vq.w), hayj);

            hayk = __hfma2(as_h2(vp.x), as_h2(vr.x), hayk);
            hayk = __hfma2(as_h2(vp.y), as_h2(vr.y), hayk);
            hayk = __hfma2(as_h2(vp.z), as_h2(vr.z), hayk);
            hayk = __hfma2(as_h2(vp.w), as_h2(vr.w), hayk);
        }

        float2 f;
        f = __half22float2(haxj); float axj = f.x + f.y;
        f = __half22float2(haxk); float axk = f.x + f.y;
        f = __half22float2(hayj); float ayj = f.x + f.y;
        f = __half22float2(hayk); float ayk = f.x + f.y;

        #pragma unroll
        for (int off = 16; off; off >>= 1) {
            axj += __shfl_xor_sync(0xFFFFFFFFu, axj, off);
            axk += __shfl_xor_sync(0xFFFFFFFFu, axk, off);
            ayj += __shfl_xor_sync(0xFFFFFFFFu, ayj, off);
            ayk += __shfl_xor_sync(0xFFFFFFFFu, ayk, off);
        }
        if (lane == 0) {
            const float sqi = g_sqx[i];
            const float sqj = g_sqx[j];
            const float sqk = g_sqx[k];
            const float dij = fmaxf(sqi + sqj - 2.0f * axj, 0.0f);
            const float dik = fmaxf(sqi + sqk - 2.0f * axk, 0.0f);
            const float s   = norm_s[0];
            const float s2x2 = 2.0f * s * s;   // ||y_n||^2 == norm_s^2 per row
            const float tij = fmaxf(s2x2 - 2.0f * ayj, 0.0f);
            const float tik = fmaxf(s2x2 - 2.0f * ayk, 0.0f);
            val = softplus_f(dij - dik) + softplus_f(tij - tik);
        }
    }

    __shared__ float sh[8];
    if (lane == 0) sh[warp] = val;
    __syncthreads();
    if (threadIdx.x == 0) {
        float s = 0.f;
        #pragma unroll
        for (int w = 0; w < 8; ++w) s += sh[w];
        atomicAdd(&g_accum, (double)s);
    }
}

__global__ void finalize_kernel(float* __restrict__ out) {
    out[0] = (float)(g_accum * (1.0 / (double)NTRIP));
}

// ---------------------------------------------------------------------------
extern "C" void kernel_launch(void* const* d_in, const int* in_sizes, int n_in,
                              void* d_out, int out_size) {
    const float* x      = (const float*)d_in[0];
    const float* y      = (const float*)d_in[1];
    const float* norm_s = (const float*)d_in[2];
    const int*   trips  = (const int*)d_in[3];
    float*       out    = (float*)d_out;

    prep_kernel<<<NROWS / 8, 256>>>(x, y, norm_s);
    triplet_kernel<<<(NTRIP + 7) / 8, 256>>>(trips, norm_s);
    finalize_kernel<<<1, 1>>>(out);
}